// round 2
// baseline (speedup 1.0000x reference)
#include <cuda_runtime.h>
#include <cstdint>

#define MARGIN 1.0f
#define MAX_TRIALS 50
#define BLK 256
#define MAX_B (1 << 20)
#define MAX_NB ((MAX_B + BLK - 1) / BLK)   // 4096

// Scratch (no allocations allowed in kernel_launch)
__device__ int   g_neg_pos[MAX_B];     // positions of label-0 examples, ascending
__device__ int   g_blockcnt[MAX_NB];   // per-block zero counts -> exclusive offsets
__device__ int   g_num_neg;
__device__ float g_partials[MAX_NB];

// ---------------- Threefry-2x32 (exact JAX semantics) ----------------
__device__ __forceinline__ uint32_t rotl32(uint32_t x, int d) {
    return (x << d) | (x >> (32 - d));
}

__device__ __forceinline__ void threefry2x32(uint32_t k0, uint32_t k1,
                                             uint32_t c0, uint32_t c1,
                                             uint32_t& o0, uint32_t& o1) {
    const uint32_t ks2 = k0 ^ k1 ^ 0x1BD11BDAu;
    uint32_t x0 = c0 + k0;
    uint32_t x1 = c1 + k1;
    const int R0[4] = {13, 15, 26, 6};
    const int R1[4] = {17, 29, 16, 24};
#pragma unroll
    for (int i = 0; i < 4; i++) { x0 += x1; x1 = rotl32(x1, R0[i]); x1 ^= x0; }
    x0 += k1;  x1 += ks2 + 1u;
#pragma unroll
    for (int i = 0; i < 4; i++) { x0 += x1; x1 = rotl32(x1, R1[i]); x1 ^= x0; }
    x0 += ks2; x1 += k0 + 2u;
#pragma unroll
    for (int i = 0; i < 4; i++) { x0 += x1; x1 = rotl32(x1, R0[i]); x1 ^= x0; }
    x0 += k0;  x1 += k1 + 3u;
#pragma unroll
    for (int i = 0; i < 4; i++) { x0 += x1; x1 = rotl32(x1, R1[i]); x1 ^= x0; }
    x0 += k1;  x1 += ks2 + 4u;
#pragma unroll
    for (int i = 0; i < 4; i++) { x0 += x1; x1 = rotl32(x1, R0[i]); x1 ^= x0; }
    x0 += ks2; x1 += k0 + 5u;
    o0 = x0; o1 = x1;
}

// JAX partitionable threefry random bits at 64-bit linear index j (j < 2^32 here):
// counts = (hi32(j)=0, lo32(j)=j); bits = o0 ^ o1; key(42) -> (0, 42).
__device__ __forceinline__ uint32_t jax_random_bits32(uint32_t j) {
    uint32_t o0, o1;
    threefry2x32(0u, 42u, 0u, j, o0, o1);
    return o0 ^ o1;
}

__device__ __forceinline__ float bits_to_uniform(uint32_t bits) {
    return __uint_as_float((bits >> 9) | 0x3f800000u) - 1.0f;
}

// ---------------- Pass 1: per-block count of label==0 ----------------
__global__ void count_zeros_kernel(const int* __restrict__ labels, int B) {
    int i = blockIdx.x * BLK + threadIdx.x;
    int f = (i < B && labels[i] == 0) ? 1 : 0;
    unsigned m = __ballot_sync(0xffffffffu, f);
    __shared__ int wsum[BLK / 32];
    if ((threadIdx.x & 31) == 0) wsum[threadIdx.x >> 5] = __popc(m);
    __syncthreads();
    if (threadIdx.x == 0) {
        int s = 0;
#pragma unroll
        for (int w = 0; w < BLK / 32; w++) s += wsum[w];
        g_blockcnt[blockIdx.x] = s;
    }
}

// ---------------- Pass 2: exclusive scan of block counts (single block) ----
__global__ void scan_blocks_kernel(int nb) {
    __shared__ int sh[1024];
    int t = threadIdx.x;
    int v[4];
    int base = t * 4;
    int s = 0;
#pragma unroll
    for (int k = 0; k < 4; k++) {
        int idx = base + k;
        v[k] = (idx < nb) ? g_blockcnt[idx] : 0;
        s += v[k];
    }
    sh[t] = s;
    __syncthreads();
    // Hillis-Steele inclusive scan over 1024 thread sums
    for (int off = 1; off < 1024; off <<= 1) {
        int y = (t >= off) ? sh[t - off] : 0;
        __syncthreads();
        sh[t] += y;
        __syncthreads();
    }
    int run = (t > 0) ? sh[t - 1] : 0;   // exclusive prefix for this thread's chunk
#pragma unroll
    for (int k = 0; k < 4; k++) {
        int idx = base + k;
        if (idx < nb) {
            int c = v[k];
            g_blockcnt[idx] = run;       // overwrite with exclusive offset
            run += c;
        }
    }
    if (t == 0) g_num_neg = sh[1023];
}

// ---------------- Pass 3: scatter negative positions (stable order) --------
__global__ void scatter_neg_kernel(const int* __restrict__ labels, int B) {
    int i = blockIdx.x * BLK + threadIdx.x;
    int lane = threadIdx.x & 31;
    int w = threadIdx.x >> 5;
    int f = (i < B && labels[i] == 0) ? 1 : 0;
    unsigned m = __ballot_sync(0xffffffffu, f);
    int wr = __popc(m & ((1u << lane) - 1u));
    __shared__ int woff[BLK / 32];
    if (lane == 0) woff[w] = __popc(m);
    __syncthreads();
    if (threadIdx.x == 0) {
        int r = 0;
#pragma unroll
        for (int k = 0; k < BLK / 32; k++) { int c = woff[k]; woff[k] = r; r += c; }
    }
    __syncthreads();
    if (f) g_neg_pos[g_blockcnt[blockIdx.x] + woff[w] + wr] = i;
}

// ---------------- Pass 4: main WARP loss (one thread per example) ----------
__global__ void warp_main_kernel(const float* __restrict__ scores,
                                 const int* __restrict__ labels, int B) {
    __shared__ float sh_h[MAX_TRIALS];
    __shared__ float red[BLK];
    if (threadIdx.x == 0) {
        float h = 0.0f;
#pragma unroll
        for (int j = 1; j <= MAX_TRIALS; j++) {
            h += __fdiv_rn(1.0f, (float)j);   // sequential f32 cumsum of 1/j
            sh_h[j - 1] = h;
        }
    }
    __syncthreads();

    int i = blockIdx.x * BLK + threadIdx.x;
    float per = 0.0f;
    int num_neg = g_num_neg;
    if (i < B && num_neg > 0 && labels[i] == 1) {
        float s   = scores[i];
        float nnf = (float)num_neg;
        uint32_t jbase = (uint32_t)i * (uint32_t)MAX_TRIALS;
#pragma unroll 1
        for (int t = 0; t < MAX_TRIALS; t++) {
            uint32_t bits = jax_random_bits32(jbase + (uint32_t)t);
            float u = bits_to_uniform(bits);
            int idx = (int)(u * nnf);             // f32 RN mul, trunc toward 0
            idx = min(max(idx, 0), num_neg - 1);
            int np  = g_neg_pos[idx];
            float ns = __ldg(&scores[np]);
            if (ns + MARGIN > s) {                // first violation -> trials = t
                int rank = max(1, MAX_TRIALS / (t + 1));
                per = sh_h[rank - 1] * fmaxf(MARGIN - (s - ns), 0.0f);
                break;
            }
        }
    }

    // deterministic block reduction
    red[threadIdx.x] = per;
    __syncthreads();
    for (int off = BLK / 2; off > 0; off >>= 1) {
        if (threadIdx.x < off) red[threadIdx.x] += red[threadIdx.x + off];
        __syncthreads();
    }
    if (threadIdx.x == 0) g_partials[blockIdx.x] = red[0];
}

// ---------------- Pass 5: final reduce + normalize -------------------------
__global__ void finalize_kernel(float* __restrict__ out, int nb, int B) {
    __shared__ float red[1024];
    float s = 0.0f;
    for (int k = threadIdx.x; k < nb; k += 1024) s += g_partials[k];
    red[threadIdx.x] = s;
    __syncthreads();
    for (int off = 512; off > 0; off >>= 1) {
        if (threadIdx.x < off) red[threadIdx.x] += red[threadIdx.x + off];
        __syncthreads();
    }
    if (threadIdx.x == 0) {
        int nn = g_num_neg;
        int np = B - nn;
        out[0] = (nn > 0 && np > 0) ? red[0] / (float)np : 0.0f;
    }
}

extern "C" void kernel_launch(void* const* d_in, const int* in_sizes, int n_in,
                              void* d_out, int out_size) {
    const float* scores = (const float*)d_in[0];
    const int*   labels = (const int*)d_in[1];
    float* out = (float*)d_out;
    int B  = in_sizes[0];
    int nb = (B + BLK - 1) / BLK;

    count_zeros_kernel<<<nb, BLK>>>(labels, B);
    scan_blocks_kernel<<<1, 1024>>>(nb);
    scatter_neg_kernel<<<nb, BLK>>>(labels, B);
    warp_main_kernel<<<nb, BLK>>>(scores, labels, B);
    finalize_kernel<<<1, 1024>>>(out, nb, B);
}

// round 3
// speedup vs baseline: 1.7171x; 1.7171x over previous
#include <cuda_runtime.h>
#include <cstdint>

#define MARGIN 1.0f
#define MAX_TRIALS 50
#define BLK 256
#define MAX_B (1 << 20)
#define MAX_NB ((MAX_B + BLK - 1) / BLK)   // 4096

// Scratch (no allocations allowed in kernel_launch)
__device__ float g_neg_score[MAX_B];   // scores of label-0 examples, stable order
__device__ int   g_pos_idx[MAX_B];     // original indices of label-1 examples
__device__ float g_per[MAX_B];         // per-positive loss contribution
__device__ int   g_queue[MAX_B];       // unresolved positive slots
__device__ int   g_blockcnt[MAX_NB];
__device__ int   g_num_neg;
__device__ int   g_qcount;
__device__ float g_harm[MAX_TRIALS];
__device__ float g_partials[MAX_NB];

// ---------------- Threefry-2x32 (exact JAX partitionable semantics) --------
__device__ __forceinline__ uint32_t rotl32(uint32_t x, int d) {
    return (x << d) | (x >> (32 - d));
}

__device__ __forceinline__ uint32_t jax_random_bits32(uint32_t j) {
    const uint32_t k0 = 0u, k1 = 42u;
    const uint32_t ks2 = k0 ^ k1 ^ 0x1BD11BDAu;
    uint32_t x0 = 0u + k0;          // c0 = hi32(j) = 0
    uint32_t x1 = j + k1;           // c1 = lo32(j)
    const int R0[4] = {13, 15, 26, 6};
    const int R1[4] = {17, 29, 16, 24};
#pragma unroll
    for (int i = 0; i < 4; i++) { x0 += x1; x1 = rotl32(x1, R0[i]); x1 ^= x0; }
    x0 += k1;  x1 += ks2 + 1u;
#pragma unroll
    for (int i = 0; i < 4; i++) { x0 += x1; x1 = rotl32(x1, R1[i]); x1 ^= x0; }
    x0 += ks2; x1 += k0 + 2u;
#pragma unroll
    for (int i = 0; i < 4; i++) { x0 += x1; x1 = rotl32(x1, R0[i]); x1 ^= x0; }
    x0 += k0;  x1 += k1 + 3u;
#pragma unroll
    for (int i = 0; i < 4; i++) { x0 += x1; x1 = rotl32(x1, R1[i]); x1 ^= x0; }
    x0 += k1;  x1 += ks2 + 4u;
#pragma unroll
    for (int i = 0; i < 4; i++) { x0 += x1; x1 = rotl32(x1, R0[i]); x1 ^= x0; }
    x0 += ks2; x1 += k0 + 5u;
    return x0 ^ x1;
}

__device__ __forceinline__ float bits_to_uniform(uint32_t bits) {
    return __uint_as_float((bits >> 9) | 0x3f800000u) - 1.0f;
}

// One trial -> sampled negative score. Single gather (g_neg_score is dense).
__device__ __forceinline__ float sample_neg(uint32_t j, float nnf, int num_neg) {
    float u = bits_to_uniform(jax_random_bits32(j));
    int idx = (int)(u * nnf);
    idx = min(max(idx, 0), num_neg - 1);
    return __ldg(&g_neg_score[idx]);
}

// ---------------- Pass 1: per-block count of label==0 ----------------
__global__ void count_zeros_kernel(const int* __restrict__ labels, int B) {
    int i = blockIdx.x * BLK + threadIdx.x;
    int f = (i < B && labels[i] == 0) ? 1 : 0;
    unsigned m = __ballot_sync(0xffffffffu, f);
    __shared__ int wsum[BLK / 32];
    if ((threadIdx.x & 31) == 0) wsum[threadIdx.x >> 5] = __popc(m);
    __syncthreads();
    if (threadIdx.x == 0) {
        int s = 0;
#pragma unroll
        for (int w = 0; w < BLK / 32; w++) s += wsum[w];
        g_blockcnt[blockIdx.x] = s;
    }
}

// ---------------- Pass 2: exclusive scan + per-replay init -----------------
__global__ void scan_blocks_kernel(int nb) {
    __shared__ int sh[1024];
    int t = threadIdx.x;
    int v[4];
    int base = t * 4;
    int s = 0;
#pragma unroll
    for (int k = 0; k < 4; k++) {
        int idx = base + k;
        v[k] = (idx < nb) ? g_blockcnt[idx] : 0;
        s += v[k];
    }
    sh[t] = s;
    __syncthreads();
    for (int off = 1; off < 1024; off <<= 1) {
        int y = (t >= off) ? sh[t - off] : 0;
        __syncthreads();
        sh[t] += y;
        __syncthreads();
    }
    int run = (t > 0) ? sh[t - 1] : 0;
#pragma unroll
    for (int k = 0; k < 4; k++) {
        int idx = base + k;
        if (idx < nb) {
            int c = v[k];
            g_blockcnt[idx] = run;
            run += c;
        }
    }
    if (t == 0) {
        g_num_neg = sh[1023];
        g_qcount = 0;
        float h = 0.0f;
#pragma unroll
        for (int j = 1; j <= MAX_TRIALS; j++) {
            h += __fdiv_rn(1.0f, (float)j);
            g_harm[j - 1] = h;
        }
    }
}

// ---------------- Pass 3: scatter neg scores + pos indices (stable) --------
__global__ void scatter_kernel(const int* __restrict__ labels,
                               const float* __restrict__ scores, int B) {
    int i = blockIdx.x * BLK + threadIdx.x;
    int lane = threadIdx.x & 31;
    int w = threadIdx.x >> 5;
    int f = (i < B && labels[i] == 0) ? 1 : 0;
    unsigned m = __ballot_sync(0xffffffffu, f);
    int wr = __popc(m & ((1u << lane) - 1u));
    __shared__ int woff[BLK / 32];
    if (lane == 0) woff[w] = __popc(m);
    __syncthreads();
    if (threadIdx.x == 0) {
        int r = 0;
#pragma unroll
        for (int k = 0; k < BLK / 32; k++) { int c = woff[k]; woff[k] = r; r += c; }
    }
    __syncthreads();
    if (i < B) {
        int neg_before = g_blockcnt[blockIdx.x] + woff[w] + wr;  // negs strictly before i
        if (f) g_neg_score[neg_before] = scores[i];
        else   g_pos_idx[i - neg_before] = i;
    }
}

// ---------------- Phase 1: first 4 trials, ILP-4 + MLP-4 -------------------
__global__ void phase1_kernel(const float* __restrict__ scores, int B) {
    int p = blockIdx.x * BLK + threadIdx.x;
    int num_neg = g_num_neg;
    int num_pos = B - num_neg;
    if (p >= num_pos) return;
    if (num_neg <= 0) { g_per[p] = 0.0f; return; }

    int i = g_pos_idx[p];
    float s = __ldg(&scores[i]);
    float nnf = (float)num_neg;
    uint32_t jb = (uint32_t)i * (uint32_t)MAX_TRIALS;

    float ns[4];
#pragma unroll
    for (int k = 0; k < 4; k++) ns[k] = sample_neg(jb + (uint32_t)k, nnf, num_neg);

    float per = 0.0f;
    bool resolved = false;
#pragma unroll
    for (int k = 0; k < 4; k++) {
        if (!resolved && ns[k] + MARGIN > s) {
            int rank = max(1, MAX_TRIALS / (k + 1));
            per = __ldg(&g_harm[rank - 1]) * fmaxf(MARGIN - (s - ns[k]), 0.0f);
            resolved = true;
        }
    }
    g_per[p] = per;
    if (!resolved) {
        int q = atomicAdd(&g_qcount, 1);
        g_queue[q] = p;
    }
}

// ---------------- Phase 2: trials 4..49 for unresolved (dense) -------------
__global__ void phase2_kernel(const float* __restrict__ scores) {
    int n = g_qcount;
    int num_neg = g_num_neg;
    float nnf = (float)num_neg;
    for (int q = blockIdx.x * blockDim.x + threadIdx.x; q < n;
         q += gridDim.x * blockDim.x) {
        int p = g_queue[q];
        int i = g_pos_idx[p];
        float s = __ldg(&scores[i]);
        uint32_t jb = (uint32_t)i * (uint32_t)MAX_TRIALS;
        float per = 0.0f;
        bool done = false;
#pragma unroll 1
        for (int tb = 4; tb < MAX_TRIALS && !done; tb += 4) {
            float ns[4];
            int nk = min(4, MAX_TRIALS - tb);
#pragma unroll
            for (int k = 0; k < 4; k++)
                if (k < nk) ns[k] = sample_neg(jb + (uint32_t)(tb + k), nnf, num_neg);
#pragma unroll
            for (int k = 0; k < 4; k++) {
                if (!done && k < nk && ns[k] + MARGIN > s) {
                    int t = tb + k;
                    int rank = max(1, MAX_TRIALS / (t + 1));
                    per = __ldg(&g_harm[rank - 1]) * fmaxf(MARGIN - (s - ns[k]), 0.0f);
                    done = true;
                }
            }
        }
        if (done) g_per[p] = per;   // else stays 0 from phase 1
    }
}

// ---------------- Reduce: per-block partials over positives ----------------
__global__ void reduce_kernel(int B) {
    __shared__ float red[BLK];
    int p = blockIdx.x * BLK + threadIdx.x;
    int num_pos = B - g_num_neg;
    red[threadIdx.x] = (p < num_pos) ? g_per[p] : 0.0f;
    __syncthreads();
    for (int off = BLK / 2; off > 0; off >>= 1) {
        if (threadIdx.x < off) red[threadIdx.x] += red[threadIdx.x + off];
        __syncthreads();
    }
    if (threadIdx.x == 0) g_partials[blockIdx.x] = red[0];
}

// ---------------- Finalize -------------------------------------------------
__global__ void finalize_kernel(float* __restrict__ out, int nb, int B) {
    __shared__ float red[1024];
    float s = 0.0f;
    for (int k = threadIdx.x; k < nb; k += 1024) s += g_partials[k];
    red[threadIdx.x] = s;
    __syncthreads();
    for (int off = 512; off > 0; off >>= 1) {
        if (threadIdx.x < off) red[threadIdx.x] += red[threadIdx.x + off];
        __syncthreads();
    }
    if (threadIdx.x == 0) {
        int nn = g_num_neg;
        int np = B - nn;
        out[0] = (nn > 0 && np > 0) ? red[0] / (float)np : 0.0f;
    }
}

extern "C" void kernel_launch(void* const* d_in, const int* in_sizes, int n_in,
                              void* d_out, int out_size) {
    const float* scores = (const float*)d_in[0];
    const int*   labels = (const int*)d_in[1];
    float* out = (float*)d_out;
    int B  = in_sizes[0];
    int nb = (B + BLK - 1) / BLK;

    count_zeros_kernel<<<nb, BLK>>>(labels, B);
    scan_blocks_kernel<<<1, 1024>>>(nb);
    scatter_kernel<<<nb, BLK>>>(labels, scores, B);
    phase1_kernel<<<nb, BLK>>>(scores, B);
    phase2_kernel<<<592, BLK>>>(scores);
    reduce_kernel<<<nb, BLK>>>(B);
    finalize_kernel<<<1, 1024>>>(out, nb, B);
}